// round 2
// baseline (speedup 1.0000x reference)
#include <cuda_runtime.h>

#define NN 64
#define TT 512
#define VV 25
#define CIN 3
#define CH 64
#define FF 25
#define G4 100          // 4*FF

#define TCHUNK 8        // t per block in kernel 1
#define VB 5            // joints per block in kernel 2
#define TCH3 4          // t per block in kernel 3

// Scratch (device globals: allocation-free rule)
__device__ float g_zx[NN * TT * VV * G4];   // (n,t,v,g)  327.7 MB
__device__ float g_f1[NN * TT * VV * FF];   // (n,t,v,f)   81.9 MB

__device__ __forceinline__ float hsig(float x) {
    return __saturatef(fmaf(0.2f, x, 0.5f));
}

// ---------------------------------------------------------------------------
// Kernel 1: zx[n,t,v,:] = relu(x[n,t,v,:] @ Wc + bc) @ Wl + bl
// Block = (n, 8 t's), 128 threads. W_lstm column per thread in registers,
// x1 row tile in shared, broadcast LDS.128 feeds 4 FMAs.
// ---------------------------------------------------------------------------
__global__ __launch_bounds__(128) void k_conv_z(
    const float* __restrict__ X,
    const float* __restrict__ Wc, const float* __restrict__ bc,
    const float* __restrict__ Wl, const float* __restrict__ bl)
{
    __shared__ float wc_s[CIN * CH];
    __shared__ float bc_s[CH];
    __shared__ __align__(16) float x1s[VV * CH];

    const int tid = threadIdx.x;
    const int n = blockIdx.y;
    const int t0 = blockIdx.x * TCHUNK;

    for (int i = tid; i < CIN * CH; i += 128) wc_s[i] = Wc[i];   // FIX: strided
    if (tid < CH) bc_s[tid] = bc[tid];

    const int g = tid;
    float w[CH];
    float blr = 0.f;
    if (g < G4) {
        blr = bl[g];
#pragma unroll
        for (int c = 0; c < CH; ++c) w[c] = Wl[c * G4 + g];
    }
    __syncthreads();

    for (int tt = 0; tt < TCHUNK; ++tt) {
        const int t = t0 + tt;
        const int rowbase = (n * TT + t) * VV;   // row of (n,t,0)

        // stage 1: x1 tile (25 x 64) in shared
        for (int idx = tid; idx < VV * CH; idx += 128) {
            const int v = idx >> 6, c = idx & 63;
            const float* xr = X + (rowbase + v) * CIN;
            float a = bc_s[c];
            a = fmaf(xr[0], wc_s[c],          a);
            a = fmaf(xr[1], wc_s[CH + c],     a);
            a = fmaf(xr[2], wc_s[2 * CH + c], a);
            x1s[idx] = fmaxf(a, 0.f);
        }
        __syncthreads();

        // stage 2: z = x1 @ Wl + bl
        if (g < G4) {
            float* zbase = g_zx + (size_t)rowbase * G4 + g;
            for (int v = 0; v < VV; ++v) {
                const float4* xv = (const float4*)(x1s + v * CH);
                float a0 = blr, a1 = 0.f;
#pragma unroll
                for (int q = 0; q < CH / 4; ++q) {
                    float4 p = xv[q];
                    a0 = fmaf(p.x, w[4 * q + 0], a0);
                    a1 = fmaf(p.y, w[4 * q + 1], a1);
                    a0 = fmaf(p.z, w[4 * q + 2], a0);
                    a1 = fmaf(p.w, w[4 * q + 3], a1);
                }
                zbase[v * G4] = a0 + a1;
            }
        }
        __syncthreads();
    }
}

// ---------------------------------------------------------------------------
// Kernel 2: ConvLSTM recurrence. Block = (n, 5 joints), 512 threads.
// Thread (vl, g) computes gate g for joint vl; U column in registers.
// Writer threads (vl, j<25) hold cell state, apply activations, write h.
// ---------------------------------------------------------------------------
__global__ __launch_bounds__(512) void k_lstm(const float* __restrict__ U)
{
    __shared__ __align__(16) float h_s[VB][28];   // padded, [25..27]=0
    __shared__ float gs[VB][G4];

    const int tid = threadIdx.x;
    const int n = blockIdx.y;
    const int v0 = blockIdx.x * VB;
    const int g = tid % G4;
    const int vl = tid / G4;
    const bool act = tid < VB * G4;

    float u[28];
#pragma unroll
    for (int f = 0; f < FF; ++f) u[f] = U[f * G4 + g];
    u[25] = u[26] = u[27] = 0.f;

    for (int i = tid; i < VB * 28; i += 512) ((float*)h_s)[i] = 0.f;

    const int wj = tid % FF, wv = tid / FF;   // writer mapping (tid < 125)
    float cst = 0.f;
    __syncthreads();

    float zc = act ? g_zx[(size_t)((n * TT + 0) * VV + v0 + vl) * G4 + g] : 0.f;

    for (int t = 0; t < TT; ++t) {
        float zn = 0.f;
        if (act && t + 1 < TT)
            zn = g_zx[(size_t)((n * TT + t + 1) * VV + v0 + vl) * G4 + g];

        if (act) {
            const float4* h4 = (const float4*)h_s[vl];
            float a0 = zc, a1 = 0.f;
#pragma unroll
            for (int q = 0; q < 7; ++q) {
                float4 p = h4[q];
                a0 = fmaf(p.x, u[4 * q + 0], a0);
                a1 = fmaf(p.y, u[4 * q + 1], a1);
                a0 = fmaf(p.z, u[4 * q + 2], a0);
                a1 = fmaf(p.w, u[4 * q + 3], a1);
            }
            gs[vl][g] = a0 + a1;
        }
        __syncthreads();

        if (tid < VB * FF) {
            const float gi = hsig(gs[wv][wj]);
            const float gf = hsig(gs[wv][FF + wj]);
            const float gg = tanhf(gs[wv][2 * FF + wj]);
            const float go = hsig(gs[wv][3 * FF + wj]);
            cst = gf * cst + gi * gg;
            const float h = go * tanhf(cst);
            h_s[wv][wj] = h;
            g_f1[(size_t)((n * TT + t) * VV + v0 + wv) * FF + wj] = h;
        }
        __syncthreads();
        zc = zn;
    }
}

// ---------------------------------------------------------------------------
// Kernel 3: attention + aggregation. Block = (n, 4 t's), 128 threads.
// Recomputes x1 (transposed in shared), softmax(leaky(h)+bias), out = coefs@x1.
// ---------------------------------------------------------------------------
__global__ __launch_bounds__(128) void k_attn(
    const float* __restrict__ X,
    const float* __restrict__ Wc, const float* __restrict__ bc,
    const float* __restrict__ Bm, float* __restrict__ out)
{
    __shared__ float wc_s[CIN * CH];
    __shared__ float bc_s[CH];
    __shared__ float bias_s[VV * VV];
    __shared__ __align__(16) float x1T[CH][28];   // x1 transposed, padded
    __shared__ float fs[VV * VV];
    __shared__ __align__(16) float cf[VV][28];    // coefs, padded

    const int tid = threadIdx.x;
    const int n = blockIdx.y;
    const int t0 = blockIdx.x * TCH3;

    for (int i = tid; i < CIN * CH; i += 128) wc_s[i] = Wc[i];   // FIX: strided
    if (tid < CH) bc_s[tid] = bc[tid];
    for (int i = tid; i < VV * VV; i += 128) bias_s[i] = Bm[i];
    if (tid < CH) { x1T[tid][25] = 0.f; x1T[tid][26] = 0.f; x1T[tid][27] = 0.f; }
    if (tid < VV) { cf[tid][25] = 0.f;  cf[tid][26] = 0.f;  cf[tid][27] = 0.f; }
    __syncthreads();

    for (int tt = 0; tt < TCH3; ++tt) {
        const int t = t0 + tt;
        const int rowbase = (n * TT + t) * VV;

        // recompute x1, store transposed [c][v]
        for (int idx = tid; idx < VV * CH; idx += 128) {
            const int v = idx >> 6, c = idx & 63;
            const float* xr = X + (rowbase + v) * CIN;
            float a = bc_s[c];
            a = fmaf(xr[0], wc_s[c],          a);
            a = fmaf(xr[1], wc_s[CH + c],     a);
            a = fmaf(xr[2], wc_s[2 * CH + c], a);
            x1T[c][v] = fmaxf(a, 0.f);
        }
        // load f1 tile (25x25)
        for (int i = tid; i < VV * VV; i += 128)
            fs[i] = g_f1[(size_t)rowbase * FF + i];
        __syncthreads();

        // softmax over last axis; args bounded in [-0.2, 1.01] -> no max-sub
        if (tid < VV) {
            const int v = tid;
            float e[VV];
            float s = 0.f;
#pragma unroll
            for (int w_ = 0; w_ < VV; ++w_) {
                const float hv = fs[v * VV + w_];
                const float lr = hv > 0.f ? hv : 0.2f * hv;
                const float ev = __expf(lr + bias_s[v * VV + w_]);
                e[w_] = ev; s += ev;
            }
            const float inv = 1.0f / s;
#pragma unroll
            for (int w_ = 0; w_ < VV; ++w_) cf[v][w_] = e[w_] * inv;
        }
        __syncthreads();

        // out[v][c] = sum_w cf[v][w] * x1[w][c]
        {
            const int c = tid & 63, vb = tid >> 6;
            for (int v = vb; v < VV; v += 2) {
                const float4* cfv = (const float4*)cf[v];
                const float4* xc  = (const float4*)x1T[c];
                float a0 = 0.f, a1 = 0.f;
#pragma unroll
                for (int q = 0; q < 7; ++q) {
                    float4 p = cfv[q], xq = xc[q];
                    a0 = fmaf(p.x, xq.x, a0);
                    a1 = fmaf(p.y, xq.y, a1);
                    a0 = fmaf(p.z, xq.z, a0);
                    a1 = fmaf(p.w, xq.w, a1);
                }
                out[(size_t)(rowbase + v) * CH + c] = a0 + a1;
            }
        }
        __syncthreads();
    }
}

// ---------------------------------------------------------------------------
extern "C" void kernel_launch(void* const* d_in, const int* in_sizes, int n_in,
                              void* d_out, int out_size)
{
    const float* X  = (const float*)d_in[0];  // (N,T,V,CIN)
    const float* Wc = (const float*)d_in[1];  // (CIN,CH)
    const float* bc = (const float*)d_in[2];  // (CH)
    const float* Wl = (const float*)d_in[3];  // (CH,4F)
    const float* Ul = (const float*)d_in[4];  // (F,4F)
    const float* bl = (const float*)d_in[5];  // (4F)
    const float* Bm = (const float*)d_in[6];  // (V,V)
    float* out = (float*)d_out;               // (N,T,V,CH)

    k_conv_z<<<dim3(TT / TCHUNK, NN), 128>>>(X, Wc, bc, Wl, bl);
    k_lstm  <<<dim3(VV / VB, NN),    512>>>(Ul);
    k_attn  <<<dim3(TT / TCH3, NN),  128>>>(X, Wc, bc, Bm, out);
}

// round 9
// speedup vs baseline: 1.4638x; 1.4638x over previous
#include <cuda_runtime.h>
#include <cstdint>

#define NN 64
#define TT 512
#define VV 25
#define CIN 3
#define CH 64
#define FF 25
#define G4 100          // 4*FF

#define TCHUNK 8        // t per block in kernel 1

// Scratch (device globals: allocation-free rule)
__device__ float g_zx[NN * TT * VV * G4];   // (n,t,v,g)  327.7 MB
__device__ float g_f1[NN * TT * VV * FF];   // (n,t,v,f)   81.9 MB

__device__ __forceinline__ float hsig(float x) {
    return __saturatef(fmaf(0.2f, x, 0.5f));
}

// ---------------------------------------------------------------------------
// Kernel 1: zx[n,t,v,:] = relu(x[n,t,v,:] @ Wc + bc) @ Wl + bl
// (unchanged from R2 passing version: 432 us measured)
// ---------------------------------------------------------------------------
__global__ __launch_bounds__(128) void k_conv_z(
    const float* __restrict__ X,
    const float* __restrict__ Wc, const float* __restrict__ bc,
    const float* __restrict__ Wl, const float* __restrict__ bl)
{
    __shared__ float wc_s[CIN * CH];
    __shared__ float bc_s[CH];
    __shared__ __align__(16) float x1s[VV * CH];

    const int tid = threadIdx.x;
    const int n = blockIdx.y;
    const int t0 = blockIdx.x * TCHUNK;

    for (int i = tid; i < CIN * CH; i += 128) wc_s[i] = Wc[i];
    if (tid < CH) bc_s[tid] = bc[tid];

    const int g = tid;
    float w[CH];
    float blr = 0.f;
    if (g < G4) {
        blr = bl[g];
#pragma unroll
        for (int c = 0; c < CH; ++c) w[c] = Wl[c * G4 + g];
    }
    __syncthreads();

    for (int tt = 0; tt < TCHUNK; ++tt) {
        const int t = t0 + tt;
        const int rowbase = (n * TT + t) * VV;

        for (int idx = tid; idx < VV * CH; idx += 128) {
            const int v = idx >> 6, c = idx & 63;
            const float* xr = X + (rowbase + v) * CIN;
            float a = bc_s[c];
            a = fmaf(xr[0], wc_s[c],          a);
            a = fmaf(xr[1], wc_s[CH + c],     a);
            a = fmaf(xr[2], wc_s[2 * CH + c], a);
            x1s[idx] = fmaxf(a, 0.f);
        }
        __syncthreads();

        if (g < G4) {
            float* zbase = g_zx + (size_t)rowbase * G4 + g;
            for (int v = 0; v < VV; ++v) {
                const float4* xv = (const float4*)(x1s + v * CH);
                float a0 = blr, a1 = 0.f;
#pragma unroll
                for (int q = 0; q < CH / 4; ++q) {
                    float4 p = xv[q];
                    a0 = fmaf(p.x, w[4 * q + 0], a0);
                    a1 = fmaf(p.y, w[4 * q + 1], a1);
                    a0 = fmaf(p.z, w[4 * q + 2], a0);
                    a1 = fmaf(p.w, w[4 * q + 3], a1);
                }
                zbase[v * G4] = a0 + a1;
            }
        }
        __syncthreads();
    }
}

// ---------------------------------------------------------------------------
// Kernel 2: ConvLSTM recurrence, warp-per-(n,v), barrier-free.
// Lane j (j<25) owns gates (j, 25+j, 50+j, 75+j) and h[j]; U columns in
// registers; h broadcast via shfl; z prefetched one step ahead.
// ---------------------------------------------------------------------------
__global__ __launch_bounds__(128) void k_lstm(const float* __restrict__ U)
{
    const int lane = threadIdx.x & 31;
    const int wrp  = threadIdx.x >> 5;
    const int seq  = blockIdx.x * 4 + wrp;       // 0..1599
    const int n = seq / VV, v = seq % VV;
    const bool act = lane < FF;

    // U columns for this lane's 4 gates
    float ui[FF], uf[FF], ug[FF], uo[FF];
#pragma unroll
    for (int c = 0; c < FF; ++c) {
        const float* Ur = U + c * G4;
        ui[c] = act ? Ur[lane]           : 0.f;
        uf[c] = act ? Ur[FF + lane]      : 0.f;
        ug[c] = act ? Ur[2 * FF + lane]  : 0.f;
        uo[c] = act ? Ur[3 * FF + lane]  : 0.f;
    }

    const size_t zstride = (size_t)VV * G4;      // per-t stride in g_zx
    const float* zrow = g_zx + ((size_t)(n * TT) * VV + v) * G4;

    float h = 0.f, cst = 0.f;

    // prefetch t=0
    float zi = act ? zrow[lane]          : 0.f;
    float zf = act ? zrow[FF + lane]     : 0.f;
    float zg = act ? zrow[2 * FF + lane] : 0.f;
    float zo = act ? zrow[3 * FF + lane] : 0.f;

    float* frow = g_f1 + ((size_t)(n * TT) * VV + v) * FF;

    for (int t = 0; t < TT; ++t) {
        // prefetch t+1
        float pi = 0.f, pf = 0.f, pg = 0.f, po = 0.f;
        if (t + 1 < TT && act) {
            const float* zn = zrow + (size_t)(t + 1) * zstride;
            pi = zn[lane]; pf = zn[FF + lane];
            pg = zn[2 * FF + lane]; po = zn[3 * FF + lane];
        }

        float gi = zi, gf = zf, gg = zg, go = zo;
#pragma unroll
        for (int c = 0; c < FF; ++c) {
            const float hc = __shfl_sync(0xFFFFFFFFu, h, c);
            gi = fmaf(hc, ui[c], gi);
            gf = fmaf(hc, uf[c], gf);
            gg = fmaf(hc, ug[c], gg);
            go = fmaf(hc, uo[c], go);
        }
        cst = hsig(gf) * cst + hsig(gi) * tanhf(gg);
        h = hsig(go) * tanhf(cst);

        if (act) frow[(size_t)t * (VV * FF) + lane] = h;

        zi = pi; zf = pf; zg = pg; zo = po;
    }
}

// ---------------------------------------------------------------------------
// Kernel 3: attention + aggregation, warp-per-timestep (no block barriers
// in the t loop). 4 warps/block, each warp does 4 consecutive t's.
// ---------------------------------------------------------------------------
__global__ __launch_bounds__(128) void k_attn(
    const float* __restrict__ X,
    const float* __restrict__ Wc, const float* __restrict__ bc,
    const float* __restrict__ Bm, float* __restrict__ out)
{
    __shared__ float wc_s[CIN * CH];
    __shared__ float bc_s[CH];
    __shared__ float bias_s[VV * VV];
    __shared__ __align__(16) float x1w[4][VV * CH];   // per-warp x1 [v][c]
    __shared__ float cfw[4][26 * 28];                 // per-warp coefs, padded

    const int tid = threadIdx.x;
    const int lane = tid & 31, wrp = tid >> 5;
    const int n = blockIdx.y;
    const int t0 = blockIdx.x * 16 + wrp * 4;

    for (int i = tid; i < CIN * CH; i += 128) wc_s[i] = Wc[i];
    if (tid < CH) bc_s[tid] = bc[tid];
    for (int i = tid; i < VV * VV; i += 128) bias_s[i] = Bm[i];
    __syncthreads();

    float* x1s = x1w[wrp];
    float* cfs = cfw[wrp];
    const int cq = lane & 15, vg = lane >> 4;
    const int vbase = vg ? 13 : 0;
    const int nv = vg ? 12 : 13;

    for (int it = 0; it < 4; ++it) {
        const int t = t0 + it;
        const int rowbase = (n * TT + t) * VV;

        // x1 recompute into per-warp shared [v][c]
        for (int idx = lane; idx < VV * CH; idx += 32) {
            const int v = idx >> 6, c = idx & 63;
            const float* xr = X + (size_t)(rowbase + v) * CIN;
            float a = bc_s[c];
            a = fmaf(xr[0], wc_s[c], a);
            a = fmaf(xr[1], wc_s[CH + c], a);
            a = fmaf(xr[2], wc_s[2 * CH + c], a);
            x1s[idx] = fmaxf(a, 0.f);
        }

        // softmax: lane-per-row v
        if (lane < VV) {
            const int v = lane;
            const float* fr = g_f1 + (size_t)rowbase * FF + v * FF;
            float e[VV], s = 0.f;
#pragma unroll
            for (int w_ = 0; w_ < VV; ++w_) {
                const float hv = fr[w_];
                const float lr = hv > 0.f ? hv : 0.2f * hv;
                const float ev = __expf(lr + bias_s[v * VV + w_]);
                e[w_] = ev; s += ev;
            }
            const float inv = 1.0f / s;
#pragma unroll
            for (int w_ = 0; w_ < VV; ++w_) cfs[v * 28 + w_] = e[w_] * inv;
        }
        __syncwarp();

        // aggregation: lane = (vg, cq); 13 (or 12) v's per lane, 4 channels
        {
            float4 acc[13];
#pragma unroll
            for (int i = 0; i < 13; ++i) acc[i] = make_float4(0.f, 0.f, 0.f, 0.f);
            const float4* x4 = (const float4*)x1s;
#pragma unroll
            for (int w_ = 0; w_ < VV; ++w_) {
                const float4 xv = x4[w_ * 16 + cq];
#pragma unroll
                for (int vl = 0; vl < 13; ++vl) {
                    const float cv = cfs[(vbase + vl) * 28 + w_];
                    acc[vl].x = fmaf(cv, xv.x, acc[vl].x);
                    acc[vl].y = fmaf(cv, xv.y, acc[vl].y);
                    acc[vl].z = fmaf(cv, xv.z, acc[vl].z);
                    acc[vl].w = fmaf(cv, xv.w, acc[vl].w);
                }
            }
#pragma unroll
            for (int vl = 0; vl < 13; ++vl) {
                if (vl < nv) {
                    const int v = vbase + vl;
                    *(float4*)(out + (size_t)(rowbase + v) * CH + cq * 4) = acc[vl];
                }
            }
        }
        __syncwarp();
    }
}

// ---------------------------------------------------------------------------
extern "C" void kernel_launch(void* const* d_in, const int* in_sizes, int n_in,
                              void* d_out, int out_size)
{
    const float* X  = (const float*)d_in[0];
    const float* Wc = (const float*)d_in[1];
    const float* bc = (const float*)d_in[2];
    const float* Wl = (const float*)d_in[3];
    const float* Ul = (const float*)d_in[4];
    const float* bl = (const float*)d_in[5];
    const float* Bm = (const float*)d_in[6];
    float* out = (float*)d_out;

    k_conv_z<<<dim3(TT / TCHUNK, NN), 128>>>(X, Wc, bc, Wl, bl);
    k_lstm<<<NN * VV / 4, 128>>>(Ul);
    k_attn<<<dim3(TT / 16, NN), 128>>>(X, Wc, bc, Bm, out);
}

// round 12
// speedup vs baseline: 1.4728x; 1.0061x over previous
#include <cuda_runtime.h>
#include <cstdint>

#define NN 64
#define TT 512
#define VV 25
#define CIN 3
#define CH 64
#define FF 25
#define G4 100          // 4*FF

#define TCHUNK 8        // t per block in kernel 1

// Scratch (device globals: allocation-free rule)
__device__ float g_zx[NN * TT * VV * G4];   // (n,t,v,g)  327.7 MB
__device__ float g_f1[NN * TT * VV * FF];   // (n,t,v,f)   81.9 MB

__device__ __forceinline__ float hsig(float x) {
    return __saturatef(fmaf(0.2f, x, 0.5f));
}

// ---- packed f32x2 helpers (Blackwell sm_100+ base feature) ----------------
__device__ __forceinline__ uint64_t pack2(float lo, float hi) {
    uint64_t r;
    asm("mov.b64 %0, {%1, %2};" : "=l"(r) : "f"(lo), "f"(hi));
    return r;
}
__device__ __forceinline__ void ffma2(uint64_t& d, uint64_t a, uint64_t b) {
    asm("fma.rn.f32x2 %0, %1, %2, %0;" : "+l"(d) : "l"(a), "l"(b));
}
__device__ __forceinline__ float hsum2(uint64_t v) {
    float lo, hi;
    asm("mov.b64 {%0, %1}, %2;" : "=f"(lo), "=f"(hi) : "l"(v));
    return lo + hi;
}

// ---------------------------------------------------------------------------
// Kernel 1: zx[n,t,v,:] = relu(x[n,t,v,:] @ Wc + bc) @ Wl + bl
// Stage 2 uses packed fma.rn.f32x2 (FFMA2): 2 MACs per issue slot.
// ---------------------------------------------------------------------------
__global__ __launch_bounds__(128) void k_conv_z(
    const float* __restrict__ X,
    const float* __restrict__ Wc, const float* __restrict__ bc,
    const float* __restrict__ Wl, const float* __restrict__ bl)
{
    __shared__ float wc_s[CIN * CH];
    __shared__ float bc_s[CH];
    __shared__ __align__(16) float x1s[VV * CH];

    const int tid = threadIdx.x;
    const int n = blockIdx.y;
    const int t0 = blockIdx.x * TCHUNK;

    for (int i = tid; i < CIN * CH; i += 128) wc_s[i] = Wc[i];
    if (tid < CH) bc_s[tid] = bc[tid];

    const int g = tid;
    uint64_t w2[CH / 2];      // packed weight pairs: w2[j] = {Wl[2j][g], Wl[2j+1][g]}
    float blr = 0.f;
    if (g < G4) {
        blr = bl[g];
#pragma unroll
        for (int j = 0; j < CH / 2; ++j)
            w2[j] = pack2(Wl[(2 * j) * G4 + g], Wl[(2 * j + 1) * G4 + g]);
    }
    __syncthreads();

    for (int tt = 0; tt < TCHUNK; ++tt) {
        const int t = t0 + tt;
        const int rowbase = (n * TT + t) * VV;

        // stage 1: x1 tile (25 x 64) in shared
        for (int idx = tid; idx < VV * CH; idx += 128) {
            const int v = idx >> 6, c = idx & 63;
            const float* xr = X + (rowbase + v) * CIN;
            float a = bc_s[c];
            a = fmaf(xr[0], wc_s[c],          a);
            a = fmaf(xr[1], wc_s[CH + c],     a);
            a = fmaf(xr[2], wc_s[2 * CH + c], a);
            x1s[idx] = fmaxf(a, 0.f);
        }
        __syncthreads();

        // stage 2: z = x1 @ Wl + bl  (packed f32x2)
        if (g < G4) {
            float* zbase = g_zx + (size_t)rowbase * G4 + g;
            for (int v = 0; v < VV; ++v) {
                const ulonglong2* xv = (const ulonglong2*)(x1s + v * CH);
                uint64_t a0 = pack2(blr, 0.f);
                uint64_t a1 = 0, a2 = 0, a3 = 0;
#pragma unroll
                for (int q = 0; q < 8; ++q) {
                    ulonglong2 p0 = xv[2 * q];         // floats {8q..8q+3}
                    ulonglong2 p1 = xv[2 * q + 1];     // floats {8q+4..8q+7}
                    ffma2(a0, p0.x, w2[4 * q + 0]);
                    ffma2(a1, p0.y, w2[4 * q + 1]);
                    ffma2(a2, p1.x, w2[4 * q + 2]);
                    ffma2(a3, p1.y, w2[4 * q + 3]);
                }
                zbase[v * G4] = (hsum2(a0) + hsum2(a1)) + (hsum2(a2) + hsum2(a3));
            }
        }
        __syncthreads();
    }
}

// ---------------------------------------------------------------------------
// Kernel 2: ConvLSTM recurrence, warp-per-(n,v), barrier-free.
// (unchanged from R9 passing version)
// ---------------------------------------------------------------------------
__global__ __launch_bounds__(128) void k_lstm(const float* __restrict__ U)
{
    const int lane = threadIdx.x & 31;
    const int wrp  = threadIdx.x >> 5;
    const int seq  = blockIdx.x * 4 + wrp;       // 0..1599
    const int n = seq / VV, v = seq % VV;
    const bool act = lane < FF;

    float ui[FF], uf[FF], ug[FF], uo[FF];
#pragma unroll
    for (int c = 0; c < FF; ++c) {
        const float* Ur = U + c * G4;
        ui[c] = act ? Ur[lane]           : 0.f;
        uf[c] = act ? Ur[FF + lane]      : 0.f;
        ug[c] = act ? Ur[2 * FF + lane]  : 0.f;
        uo[c] = act ? Ur[3 * FF + lane]  : 0.f;
    }

    const size_t zstride = (size_t)VV * G4;
    const float* zrow = g_zx + ((size_t)(n * TT) * VV + v) * G4;

    float h = 0.f, cst = 0.f;

    float zi = act ? zrow[lane]          : 0.f;
    float zf = act ? zrow[FF + lane]     : 0.f;
    float zg = act ? zrow[2 * FF + lane] : 0.f;
    float zo = act ? zrow[3 * FF + lane] : 0.f;

    float* frow = g_f1 + ((size_t)(n * TT) * VV + v) * FF;

    for (int t = 0; t < TT; ++t) {
        float pi = 0.f, pf = 0.f, pg = 0.f, po = 0.f;
        if (t + 1 < TT && act) {
            const float* zn = zrow + (size_t)(t + 1) * zstride;
            pi = zn[lane]; pf = zn[FF + lane];
            pg = zn[2 * FF + lane]; po = zn[3 * FF + lane];
        }

        float gi = zi, gf = zf, gg = zg, go = zo;
#pragma unroll
        for (int c = 0; c < FF; ++c) {
            const float hc = __shfl_sync(0xFFFFFFFFu, h, c);
            gi = fmaf(hc, ui[c], gi);
            gf = fmaf(hc, uf[c], gf);
            gg = fmaf(hc, ug[c], gg);
            go = fmaf(hc, uo[c], go);
        }
        cst = hsig(gf) * cst + hsig(gi) * tanhf(gg);
        h = hsig(go) * tanhf(cst);

        if (act) frow[(size_t)t * (VV * FF) + lane] = h;

        zi = pi; zf = pf; zg = pg; zo = po;
    }
}

// ---------------------------------------------------------------------------
// Kernel 3: attention + aggregation, warp-per-timestep.
// (unchanged from R9 passing version)
// ---------------------------------------------------------------------------
__global__ __launch_bounds__(128) void k_attn(
    const float* __restrict__ X,
    const float* __restrict__ Wc, const float* __restrict__ bc,
    const float* __restrict__ Bm, float* __restrict__ out)
{
    __shared__ float wc_s[CIN * CH];
    __shared__ float bc_s[CH];
    __shared__ float bias_s[VV * VV];
    __shared__ __align__(16) float x1w[4][VV * CH];
    __shared__ float cfw[4][26 * 28];

    const int tid = threadIdx.x;
    const int lane = tid & 31, wrp = tid >> 5;
    const int n = blockIdx.y;
    const int t0 = blockIdx.x * 16 + wrp * 4;

    for (int i = tid; i < CIN * CH; i += 128) wc_s[i] = Wc[i];
    if (tid < CH) bc_s[tid] = bc[tid];
    for (int i = tid; i < VV * VV; i += 128) bias_s[i] = Bm[i];
    __syncthreads();

    float* x1s = x1w[wrp];
    float* cfs = cfw[wrp];
    const int cq = lane & 15, vg = lane >> 4;
    const int vbase = vg ? 13 : 0;
    const int nv = vg ? 12 : 13;

    for (int it = 0; it < 4; ++it) {
        const int t = t0 + it;
        const int rowbase = (n * TT + t) * VV;

        for (int idx = lane; idx < VV * CH; idx += 32) {
            const int v = idx >> 6, c = idx & 63;
            const float* xr = X + (size_t)(rowbase + v) * CIN;
            float a = bc_s[c];
            a = fmaf(xr[0], wc_s[c], a);
            a = fmaf(xr[1], wc_s[CH + c], a);
            a = fmaf(xr[2], wc_s[2 * CH + c], a);
            x1s[idx] = fmaxf(a, 0.f);
        }

        if (lane < VV) {
            const int v = lane;
            const float* fr = g_f1 + (size_t)rowbase * FF + v * FF;
            float e[VV], s = 0.f;
#pragma unroll
            for (int w_ = 0; w_ < VV; ++w_) {
                const float hv = fr[w_];
                const float lr = hv > 0.f ? hv : 0.2f * hv;
                const float ev = __expf(lr + bias_s[v * VV + w_]);
                e[w_] = ev; s += ev;
            }
            const float inv = 1.0f / s;
#pragma unroll
            for (int w_ = 0; w_ < VV; ++w_) cfs[v * 28 + w_] = e[w_] * inv;
        }
        __syncwarp();

        {
            float4 acc[13];
#pragma unroll
            for (int i = 0; i < 13; ++i) acc[i] = make_float4(0.f, 0.f, 0.f, 0.f);
            const float4* x4 = (const float4*)x1s;
#pragma unroll
            for (int w_ = 0; w_ < VV; ++w_) {
                const float4 xv = x4[w_ * 16 + cq];
#pragma unroll
                for (int vl = 0; vl < 13; ++vl) {
                    const float cv = cfs[(vbase + vl) * 28 + w_];
                    acc[vl].x = fmaf(cv, xv.x, acc[vl].x);
                    acc[vl].y = fmaf(cv, xv.y, acc[vl].y);
                    acc[vl].z = fmaf(cv, xv.z, acc[vl].z);
                    acc[vl].w = fmaf(cv, xv.w, acc[vl].w);
                }
            }
#pragma unroll
            for (int vl = 0; vl < 13; ++vl) {
                if (vl < nv) {
                    const int v = vbase + vl;
                    *(float4*)(out + (size_t)(rowbase + v) * CH + cq * 4) = acc[vl];
                }
            }
        }
        __syncwarp();
    }
}

// ---------------------------------------------------------------------------
extern "C" void kernel_launch(void* const* d_in, const int* in_sizes, int n_in,
                              void* d_out, int out_size)
{
    const float* X  = (const float*)d_in[0];
    const float* Wc = (const float*)d_in[1];
    const float* bc = (const float*)d_in[2];
    const float* Wl = (const float*)d_in[3];
    const float* Ul = (const float*)d_in[4];
    const float* bl = (const float*)d_in[5];
    const float* Bm = (const float*)d_in[6];
    float* out = (float*)d_out;

    k_conv_z<<<dim3(TT / TCHUNK, NN), 128>>>(X, Wc, bc, Wl, bl);
    k_lstm<<<NN * VV / 4, 128>>>(Ul);
    k_attn<<<dim3(TT / 16, NN), 128>>>(X, Wc, bc, Bm, out);
}

// round 13
// speedup vs baseline: 1.5177x; 1.0305x over previous
#include <cuda_runtime.h>
#include <cstdint>

#define NN 64
#define TT 512
#define VV 25
#define CIN 3
#define CH 64
#define FF 25
#define G4 100          // 4*FF

#define TCHUNK 8        // t per block in kernel 1 (processed as 4 pairs)

// Scratch (device globals: allocation-free rule)
__device__ float g_zx[NN * TT * VV * G4];   // (n,t,v,g)  327.7 MB
__device__ float g_f1[NN * TT * VV * FF];   // (n,t,v,f)   81.9 MB

__device__ __forceinline__ float hsig(float x) {
    return __saturatef(fmaf(0.2f, x, 0.5f));
}

// ---- packed f32x2 helpers --------------------------------------------------
__device__ __forceinline__ uint64_t pack2(float lo, float hi) {
    uint64_t r;
    asm("mov.b64 %0, {%1, %2};" : "=l"(r) : "f"(lo), "f"(hi));
    return r;
}
__device__ __forceinline__ void ffma2(uint64_t& d, uint64_t a, uint64_t b) {
    asm("fma.rn.f32x2 %0, %1, %2, %0;" : "+l"(d) : "l"(a), "l"(b));
}
__device__ __forceinline__ float hsum2(uint64_t v) {
    float lo, hi;
    asm("mov.b64 {%0, %1}, %2;" : "=f"(lo), "=f"(hi) : "l"(v));
    return lo + hi;
}

// ---------------------------------------------------------------------------
// Kernel 1: zx[n,t,v,:] = relu(x[n,t,v,:] @ Wc + bc) @ Wl + bl
// r_g=2: thread owns gate columns (g, g+50); warps 0-1 handle even t,
// warps 2-3 odd t (own x1 tile each). Each 16B x load feeds 8 FFMA2.
// ---------------------------------------------------------------------------
__global__ __launch_bounds__(128, 2) void k_conv_z(
    const float* __restrict__ X,
    const float* __restrict__ Wc, const float* __restrict__ bc,
    const float* __restrict__ Wl, const float* __restrict__ bl)
{
    __shared__ float wc_s[CIN * CH];
    __shared__ float bc_s[CH];
    __shared__ __align__(16) float x1s[2][VV * CH];   // per-group x1 tiles

    const int tid = threadIdx.x;
    const int n = blockIdx.y;
    const int t0 = blockIdx.x * TCHUNK;

    for (int i = tid; i < CIN * CH; i += 128) wc_s[i] = Wc[i];
    if (tid < CH) bc_s[tid] = bc[tid];

    const int grp = tid >> 6;            // 0: even t, 1: odd t
    const int idx = tid & 63;            // id within group
    const int g = idx;                   // gate columns g and g+50
    const bool act = idx < 50;

    uint64_t wA[CH / 2], wB[CH / 2];     // packed c-pair weights for g, g+50
    float blA = 0.f, blB = 0.f;
    if (act) {
        blA = bl[g];
        blB = bl[g + 50];
#pragma unroll
        for (int j = 0; j < CH / 2; ++j) {
            wA[j] = pack2(Wl[(2 * j) * G4 + g],      Wl[(2 * j + 1) * G4 + g]);
            wB[j] = pack2(Wl[(2 * j) * G4 + g + 50], Wl[(2 * j + 1) * G4 + g + 50]);
        }
    }
    __syncthreads();

    for (int tp = 0; tp < TCHUNK / 2; ++tp) {
        const int tb = t0 + 2 * tp;                 // group 0 -> tb, group 1 -> tb+1

        // stage 1: both x1 tiles (2 x 25 x 64), all 128 threads
        for (int i = tid; i < 2 * VV * CH; i += 128) {
            const int tile = i / (VV * CH);
            const int rem = i - tile * (VV * CH);
            const int v = rem >> 6, c = rem & 63;
            const float* xr = X + (size_t)((n * TT + tb + tile) * VV + v) * CIN;
            float a = bc_s[c];
            a = fmaf(xr[0], wc_s[c],          a);
            a = fmaf(xr[1], wc_s[CH + c],     a);
            a = fmaf(xr[2], wc_s[2 * CH + c], a);
            x1s[tile][rem] = fmaxf(a, 0.f);
        }
        __syncthreads();

        // stage 2: each group does its own t with its own tile
        if (act) {
            const int t = tb + grp;
            const int rowbase = (n * TT + t) * VV;
            float* zbase = g_zx + (size_t)rowbase * G4;
            const float* xt = x1s[grp];
            for (int v = 0; v < VV; ++v) {
                const ulonglong2* xv = (const ulonglong2*)(xt + v * CH);
                uint64_t a0 = pack2(blA, 0.f), a1 = 0, a2 = 0, a3 = 0;
                uint64_t b0 = pack2(blB, 0.f), b1 = 0, b2 = 0, b3 = 0;
#pragma unroll
                for (int q = 0; q < 8; ++q) {
                    ulonglong2 p0 = xv[2 * q];         // floats {8q..8q+3}
                    ulonglong2 p1 = xv[2 * q + 1];     // floats {8q+4..8q+7}
                    ffma2(a0, p0.x, wA[4 * q + 0]);
                    ffma2(b0, p0.x, wB[4 * q + 0]);
                    ffma2(a1, p0.y, wA[4 * q + 1]);
                    ffma2(b1, p0.y, wB[4 * q + 1]);
                    ffma2(a2, p1.x, wA[4 * q + 2]);
                    ffma2(b2, p1.x, wB[4 * q + 2]);
                    ffma2(a3, p1.y, wA[4 * q + 3]);
                    ffma2(b3, p1.y, wB[4 * q + 3]);
                }
                zbase[v * G4 + g] =
                    (hsum2(a0) + hsum2(a1)) + (hsum2(a2) + hsum2(a3));
                zbase[v * G4 + g + 50] =
                    (hsum2(b0) + hsum2(b1)) + (hsum2(b2) + hsum2(b3));
            }
        }
        __syncthreads();
    }
}

// ---------------------------------------------------------------------------
// Kernel 2: ConvLSTM recurrence, warp-per-(n,v), barrier-free.
// (unchanged from R9/R12 passing version)
// ---------------------------------------------------------------------------
__global__ __launch_bounds__(128) void k_lstm(const float* __restrict__ U)
{
    const int lane = threadIdx.x & 31;
    const int wrp  = threadIdx.x >> 5;
    const int seq  = blockIdx.x * 4 + wrp;       // 0..1599
    const int n = seq / VV, v = seq % VV;
    const bool act = lane < FF;

    float ui[FF], uf[FF], ug[FF], uo[FF];
#pragma unroll
    for (int c = 0; c < FF; ++c) {
        const float* Ur = U + c * G4;
        ui[c] = act ? Ur[lane]           : 0.f;
        uf[c] = act ? Ur[FF + lane]      : 0.f;
        ug[c] = act ? Ur[2 * FF + lane]  : 0.f;
        uo[c] = act ? Ur[3 * FF + lane]  : 0.f;
    }

    const size_t zstride = (size_t)VV * G4;
    const float* zrow = g_zx + ((size_t)(n * TT) * VV + v) * G4;

    float h = 0.f, cst = 0.f;

    float zi = act ? zrow[lane]          : 0.f;
    float zf = act ? zrow[FF + lane]     : 0.f;
    float zg = act ? zrow[2 * FF + lane] : 0.f;
    float zo = act ? zrow[3 * FF + lane] : 0.f;

    float* frow = g_f1 + ((size_t)(n * TT) * VV + v) * FF;

    for (int t = 0; t < TT; ++t) {
        float pi = 0.f, pf = 0.f, pg = 0.f, po = 0.f;
        if (t + 1 < TT && act) {
            const float* zn = zrow + (size_t)(t + 1) * zstride;
            pi = zn[lane]; pf = zn[FF + lane];
            pg = zn[2 * FF + lane]; po = zn[3 * FF + lane];
        }

        float gi = zi, gf = zf, gg = zg, go = zo;
#pragma unroll
        for (int c = 0; c < FF; ++c) {
            const float hc = __shfl_sync(0xFFFFFFFFu, h, c);
            gi = fmaf(hc, ui[c], gi);
            gf = fmaf(hc, uf[c], gf);
            gg = fmaf(hc, ug[c], gg);
            go = fmaf(hc, uo[c], go);
        }
        cst = hsig(gf) * cst + hsig(gi) * tanhf(gg);
        h = hsig(go) * tanhf(cst);

        if (act) frow[(size_t)t * (VV * FF) + lane] = h;

        zi = pi; zf = pf; zg = pg; zo = po;
    }
}

// ---------------------------------------------------------------------------
// Kernel 3: attention + aggregation, warp-per-timestep.
// (unchanged from R9/R12 passing version)
// ---------------------------------------------------------------------------
__global__ __launch_bounds__(128) void k_attn(
    const float* __restrict__ X,
    const float* __restrict__ Wc, const float* __restrict__ bc,
    const float* __restrict__ Bm, float* __restrict__ out)
{
    __shared__ float wc_s[CIN * CH];
    __shared__ float bc_s[CH];
    __shared__ float bias_s[VV * VV];
    __shared__ __align__(16) float x1w[4][VV * CH];
    __shared__ float cfw[4][26 * 28];

    const int tid = threadIdx.x;
    const int lane = tid & 31, wrp = tid >> 5;
    const int n = blockIdx.y;
    const int t0 = blockIdx.x * 16 + wrp * 4;

    for (int i = tid; i < CIN * CH; i += 128) wc_s[i] = Wc[i];
    if (tid < CH) bc_s[tid] = bc[tid];
    for (int i = tid; i < VV * VV; i += 128) bias_s[i] = Bm[i];
    __syncthreads();

    float* x1s = x1w[wrp];
    float* cfs = cfw[wrp];
    const int cq = lane & 15, vg = lane >> 4;
    const int vbase = vg ? 13 : 0;
    const int nv = vg ? 12 : 13;

    for (int it = 0; it < 4; ++it) {
        const int t = t0 + it;
        const int rowbase = (n * TT + t) * VV;

        for (int idx = lane; idx < VV * CH; idx += 32) {
            const int v = idx >> 6, c = idx & 63;
            const float* xr = X + (size_t)(rowbase + v) * CIN;
            float a = bc_s[c];
            a = fmaf(xr[0], wc_s[c], a);
            a = fmaf(xr[1], wc_s[CH + c], a);
            a = fmaf(xr[2], wc_s[2 * CH + c], a);
            x1s[idx] = fmaxf(a, 0.f);
        }

        if (lane < VV) {
            const int v = lane;
            const float* fr = g_f1 + (size_t)rowbase * FF + v * FF;
            float e[VV], s = 0.f;
#pragma unroll
            for (int w_ = 0; w_ < VV; ++w_) {
                const float hv = fr[w_];
                const float lr = hv > 0.f ? hv : 0.2f * hv;
                const float ev = __expf(lr + bias_s[v * VV + w_]);
                e[w_] = ev; s += ev;
            }
            const float inv = 1.0f / s;
#pragma unroll
            for (int w_ = 0; w_ < VV; ++w_) cfs[v * 28 + w_] = e[w_] * inv;
        }
        __syncwarp();

        {
            float4 acc[13];
#pragma unroll
            for (int i = 0; i < 13; ++i) acc[i] = make_float4(0.f, 0.f, 0.f, 0.f);
            const float4* x4 = (const float4*)x1s;
#pragma unroll
            for (int w_ = 0; w_ < VV; ++w_) {
                const float4 xv = x4[w_ * 16 + cq];
#pragma unroll
                for (int vl = 0; vl < 13; ++vl) {
                    const float cv = cfs[(vbase + vl) * 28 + w_];
                    acc[vl].x = fmaf(cv, xv.x, acc[vl].x);
                    acc[vl].y = fmaf(cv, xv.y, acc[vl].y);
                    acc[vl].z = fmaf(cv, xv.z, acc[vl].z);
                    acc[vl].w = fmaf(cv, xv.w, acc[vl].w);
                }
            }
#pragma unroll
            for (int vl = 0; vl < 13; ++vl) {
                if (vl < nv) {
                    const int v = vbase + vl;
                    *(float4*)(out + (size_t)(rowbase + v) * CH + cq * 4) = acc[vl];
                }
            }
        }
        __syncwarp();
    }
}

// ---------------------------------------------------------------------------
extern "C" void kernel_launch(void* const* d_in, const int* in_sizes, int n_in,
                              void* d_out, int out_size)
{
    const float* X  = (const float*)d_in[0];
    const float* Wc = (const float*)d_in[1];
    const float* bc = (const float*)d_in[2];
    const float* Wl = (const float*)d_in[3];
    const float* Ul = (const float*)d_in[4];
    const float* bl = (const float*)d_in[5];
    const float* Bm = (const float*)d_in[6];
    float* out = (float*)d_out;

    k_conv_z<<<dim3(TT / TCHUNK, NN), 128>>>(X, Wc, bc, Wl, bl);
    k_lstm<<<NN * VV / 4, 128>>>(Ul);
    k_attn<<<dim3(TT / 16, NN), 128>>>(X, Wc, bc, Bm, out);
}